// round 15
// baseline (speedup 1.0000x reference)
#include <cuda_runtime.h>
#include <cuda_fp16.h>
#include <cstdint>
#include <cfloat>

// Problem constants
#define K_CODES 1024
#define DIM     256
#define BATCH   32
#define TLEN    2048
#define NROWS   (BATCH * TLEN)                 // 65536
#define QELEMS  ((size_t)BATCH * DIM * TLEN)   // 16777216
#define LOSS_OFF ((size_t)16777216)
#define IDX_OFF  ((size_t)16777217)

#define ROWS 128
#define THREADS 1024
#define KTILE  128
#define NTILES (K_CODES / KTILE)   // 8
#define AST 264                    // padded k-stride in halves (528B rows)
#define EH_BYTES (KTILE * AST * 2) // 67584 per buffer

// Scratch (no allocations allowed)
__device__ float  g_emb_t[DIM * K_CODES];   // transposed codebook [d][k]
__device__ float  g_esq[K_CODES];           // ||e_k||^2 exact (rescore)
__device__ float  g_sesq[K_CODES];          // 512 * ||e_k||^2 (approx ranking)
__device__ __half g_emb_h[K_CODES * DIM];   // fp16(1024 * e) [k][d]
__device__ double g_loss;

// Dynamic smem offsets (bytes)
#define OFF_AH    0                 // [128 rows][264 halves]
#define OFF_EH    67584             // 2 x [128 codes][264 halves]
#define OFF_SESQ  202752            // [1024] float (512*esq)
#define OFF_TMIN  206848            // [8][128] unsigned (encoded float)
#define OFF_MASK  210944            // [8][128][4] unsigned
#define OFF_WIN   227328            // [128] u64
#define OFF_XSQ   228352            // [128] float
#define OFF_MARG  228864            // [128] float
#define OFF_GMIN  229376            // [128] float
#define OFF_BIDX  229888            // [128] int
#define SMEM_SZ   230400

__device__ __forceinline__ void mma16816(float c[4], const unsigned a[4], const unsigned b[2]) {
    asm volatile(
        "mma.sync.aligned.m16n8k16.row.col.f32.f16.f16.f32 "
        "{%0,%1,%2,%3}, {%4,%5,%6,%7}, {%8,%9}, {%0,%1,%2,%3};"
        : "+f"(c[0]), "+f"(c[1]), "+f"(c[2]), "+f"(c[3])
        : "r"(a[0]), "r"(a[1]), "r"(a[2]), "r"(a[3]), "r"(b[0]), "r"(b[1]));
}

__device__ __forceinline__ void ldsm_x4(unsigned r[4], const void* p) {
    unsigned addr = (unsigned)__cvta_generic_to_shared(p);
    asm volatile("ldmatrix.sync.aligned.m8n8.x4.shared.b16 {%0,%1,%2,%3}, [%4];"
                 : "=r"(r[0]), "=r"(r[1]), "=r"(r[2]), "=r"(r[3]) : "r"(addr));
}

__device__ __forceinline__ void cp_async16(unsigned dst, const void* src) {
    asm volatile("cp.async.cg.shared.global [%0], [%1], 16;"
                 :: "r"(dst), "l"(src) : "memory");
}

// monotone float<->unsigned map
__device__ __forceinline__ unsigned fenc(float f) {
    unsigned b = __float_as_uint(f);
    return b ^ ((unsigned)((int)b >> 31) | 0x80000000u);
}
__device__ __forceinline__ float fdec(unsigned u) {
    unsigned b = u ^ (((int)u >= 0) ? 0xFFFFFFFFu : 0x80000000u);
    return __uint_as_float(b);
}

// ---------------------------------------------------------------------------
// prep: transpose codebook, ||e||^2 (+512x), fp16 scaled codebook, zero loss
// ---------------------------------------------------------------------------
__global__ void vq_prep(const float* __restrict__ emb) {
    int k = blockIdx.x;
    int d = threadIdx.x;
    float v = emb[k * DIM + d];
    g_emb_t[(size_t)d * K_CODES + k] = v;
    g_emb_h[(size_t)k * DIM + d] = __float2half(v * 1024.0f);

    __shared__ float red[DIM];
    red[d] = v * v;
    __syncthreads();
    #pragma unroll
    for (int s = DIM / 2; s > 0; s >>= 1) {
        if (d < s) red[d] += red[d + s];
        __syncthreads();
    }
    if (d == 0) { g_esq[k] = red[0]; g_sesq[k] = 512.0f * red[0]; }
    if (k == 0 && d == 0) g_loss = 0.0;
}

// ---------------------------------------------------------------------------
// main: f32-accum HMMA, 32 warps (16 rows x 32 codes each), cp.async staging.
// Round-9 structure; single change: pass-2 limit from warp-local rmin
// (superset mask, sound) -> mid-tile __syncthreads removed.
// grid: 512 blocks x 1024 threads, 225KB dyn smem (1 CTA/SM)
// ---------------------------------------------------------------------------
__global__ void __launch_bounds__(THREADS)
vq_main(const float* __restrict__ x_in, const float* __restrict__ emb,
        float* __restrict__ out) {
    extern __shared__ char sm[];
    float*  sesq = (float*)(sm + OFF_SESQ);
    unsigned* tmin = (unsigned*)(sm + OFF_TMIN);
    unsigned* cmask = (unsigned*)(sm + OFF_MASK);
    unsigned long long* winner = (unsigned long long*)(sm + OFF_WIN);
    float*  xsqs = (float*)(sm + OFF_XSQ);
    float*  margA = (float*)(sm + OFF_MARG);
    float*  gmin = (float*)(sm + OFF_GMIN);
    int*    bidx = (int*)(sm + OFF_BIDX);

    const unsigned smem_base = (unsigned)__cvta_generic_to_shared(sm);
    const int tid = threadIdx.x;
    const int blk = blockIdx.x;
    const int b   = blk >> 4;
    const int t0  = (blk & 15) * ROWS;
    const float* xbase = x_in + (size_t)b * DIM * TLEN + t0;

    // init scratch
    for (int i = tid; i < NTILES * ROWS; i += THREADS) tmin[i] = 0xFFFFFFFFu;
    for (int i = tid; i < NTILES * ROWS * 4; i += THREADS) cmask[i] = 0u;
    if (tid < ROWS) winner[tid] = ~0ull;
    for (int i = tid; i < K_CODES; i += THREADS) sesq[i] = g_sesq[i];

    // prefetch E tile 0 (64KB = 4096 x 16B)
    {
        const char* srcb = (const char*)g_emb_h;
        #pragma unroll
        for (int l = 0; l < 4; ++l) {
            int idx = tid + l * THREADS;
            int code = idx >> 5, j = idx & 31;
            cp_async16(smem_base + OFF_EH + code * (AST * 2) + j * 16,
                       srcb + code * 512 + j * 16);
        }
        asm volatile("cp.async.commit_group;" ::: "memory");
    }

    // A tile: fp16(x) as half2 pairs (coalesced along r)
    for (int i = tid; i < 128 * ROWS; i += THREADS) {
        int d2 = i >> 7, r = i & 127;
        float v0 = xbase[(size_t)(2 * d2) * TLEN + r];
        float v1 = xbase[(size_t)(2 * d2 + 1) * TLEN + r];
        *(__half2*)(sm + OFF_AH + r * (AST * 2) + d2 * 4) = __floats2half2_rn(v0, v1);
    }

    // ||x||^2 (exact sequential fp32 chain) + margin (dist'-units = 512x)
    if (tid < ROWS) {
        float s = 0.f, sa = 0.f;
        #pragma unroll 8
        for (int d = 0; d < DIM; ++d) {
            float v = xbase[(size_t)d * TLEN + tid];
            s = __fmaf_rn(v, v, s);
            sa += fabsf(v);
        }
        xsqs[tid] = s;
        margA[tid] = 512.0f * (sa * (4.0f / (1024.0f * 1024.0f)) + 3e-4f);
    }
    __syncthreads();

    const int lane = tid & 31, w = tid >> 5;
    const int g = lane >> 2, tk2 = lane & 3;
    const int r0 = (w & 7) * 16;   // warp's 16 rows
    const int c0 = (w >> 3) * 32;  // warp's 32 codes within 128-code tile

    for (int kt = 0; kt < NTILES; ++kt) {
        asm volatile("cp.async.wait_group 0;" ::: "memory");
        __syncthreads();   // tile kt staged; all warps done reading tile kt-1

        // prefetch tile kt+1 into the other buffer (overlaps this tile's MMA)
        if (kt + 1 < NTILES) {
            const char* srcb = (const char*)g_emb_h + (size_t)(kt + 1) * KTILE * DIM * 2;
            unsigned dbase = smem_base + OFF_EH + ((kt + 1) & 1) * EH_BYTES;
            #pragma unroll
            for (int l = 0; l < 4; ++l) {
                int idx = tid + l * THREADS;
                int code = idx >> 5, j = idx & 31;
                cp_async16(dbase + code * (AST * 2) + j * 16,
                           srcb + code * 512 + j * 16);
            }
            asm volatile("cp.async.commit_group;" ::: "memory");
        }

        const char* EhT = sm + OFF_EH + (kt & 1) * EH_BYTES;

        float acc[4][4];
        #pragma unroll
        for (int nn = 0; nn < 4; ++nn)
            #pragma unroll
            for (int c = 0; c < 4; ++c) acc[nn][c] = 0.f;

        #pragma unroll
        for (int kb = 0; kb < DIM; kb += 16) {
            unsigned a[4], bf[4][2];
            {
                int rowA = r0 + (lane & 15);
                int colA = kb + ((lane & 16) >> 1);
                ldsm_x4(a, sm + OFF_AH + rowA * (AST * 2) + colA * 2);
            }
            #pragma unroll
            for (int nn2 = 0; nn2 < 2; ++nn2) {
                int nrow = c0 + nn2 * 16 + (lane & 7) + ((lane & 16) >> 1);
                int colB = kb + (lane & 8);
                unsigned r4[4];
                ldsm_x4(r4, EhT + nrow * (AST * 2) + colB * 2);
                bf[2 * nn2][0] = r4[0]; bf[2 * nn2][1] = r4[1];
                bf[2 * nn2 + 1][0] = r4[2]; bf[2 * nn2 + 1][1] = r4[3];
            }
            #pragma unroll
            for (int nn = 0; nn < 4; ++nn)
                mma16816(acc[nn], a, bf[nn]);
        }

        // pass 1: dist' = 512*esq - acc; warp-local per-row min
        float sq[8];
        #pragma unroll
        for (int nn = 0; nn < 4; ++nn) {
            sq[nn * 2]     = sesq[kt * KTILE + c0 + nn * 8 + 2 * tk2];
            sq[nn * 2 + 1] = sesq[kt * KTILE + c0 + nn * 8 + 2 * tk2 + 1];
        }
        float rmin[2] = {FLT_MAX, FLT_MAX};
        #pragma unroll
        for (int nn = 0; nn < 4; ++nn)
            #pragma unroll
            for (int c = 0; c < 4; ++c) {
                float d = __fsub_rn(sq[nn * 2 + (c & 1)], acc[nn][c]);
                acc[nn][c] = d;
                rmin[c >> 1] = fminf(rmin[c >> 1], d);
            }
        // quad reduction in place: all 4 lanes hold the warp-local row min
        #pragma unroll
        for (int ch = 0; ch < 2; ++ch) {
            rmin[ch] = fminf(rmin[ch], __shfl_xor_sync(0xffffffffu, rmin[ch], 1));
            rmin[ch] = fminf(rmin[ch], __shfl_xor_sync(0xffffffffu, rmin[ch], 2));
        }
        // true tile-min for rescore gating (complete by post-loop barrier)
        if (tk2 == 0) {
            atomicMin(&tmin[kt * ROWS + r0 + g],     fenc(rmin[0]));
            atomicMin(&tmin[kt * ROWS + r0 + g + 8], fenc(rmin[1]));
        }

        // pass 2 (no barrier): limit from warp-local min -> superset mask
        float lim[2];
        #pragma unroll
        for (int ch = 0; ch < 2; ++ch)
            lim[ch] = rmin[ch] + margA[r0 + g + ch * 8];
        #pragma unroll
        for (int nn = 0; nn < 4; ++nn)
            #pragma unroll
            for (int c = 0; c < 4; ++c) {
                if (acc[nn][c] <= lim[c >> 1]) {
                    int kloc = c0 + nn * 8 + 2 * tk2 + (c & 1);
                    int row  = r0 + g + (c >> 1) * 8;
                    atomicOr(&cmask[(kt * ROWS + row) * 4 + (kloc >> 5)],
                             1u << (kloc & 31));
                }
            }
    }
    __syncthreads();

    // global approx min per row (dist'-units)
    if (tid < ROWS) {
        float m = FLT_MAX;
        #pragma unroll
        for (int t = 0; t < NTILES; ++t)
            m = fminf(m, fdec(tmin[t * ROWS + tid]));
        gmin[tid] = m;
    }
    __syncthreads();

    // exact rescore of candidates (identical fp32 fma chain as rounds 1-9)
    for (int p = tid; p < ROWS * NTILES; p += THREADS) {
        int r = p >> 3, t = p & 7;
        if (fdec(tmin[t * ROWS + r]) <= gmin[r] + margA[r]) {
            #pragma unroll
            for (int w4 = 0; w4 < 4; ++w4) {
                unsigned m = cmask[(t * ROWS + r) * 4 + w4];
                while (m) {
                    int bit = __ffs(m) - 1; m &= m - 1;
                    int k = t * KTILE + w4 * 32 + bit;
                    const float* ek = emb + (size_t)k * DIM;
                    float accv = 0.f;
                    #pragma unroll 8
                    for (int d = 0; d < DIM; ++d)
                        accv = __fmaf_rn(xbase[(size_t)d * TLEN + r], ek[d], accv);
                    float dd = __fsub_rn(__fadd_rn(xsqs[r], g_esq[k]),
                                         __fmul_rn(2.0f, accv));
                    unsigned long long key =
                        ((unsigned long long)__float_as_uint(dd) << 32) | (unsigned)k;
                    atomicMin(&winner[r], key);
                }
            }
        }
    }
    __syncthreads();

    if (tid < ROWS) {
        int bi = (int)(winner[tid] & 0xffffffffu);
        bidx[tid] = bi;
        out[IDX_OFF + (size_t)b * TLEN + t0 + tid] = (float)bi;
    }
    __syncthreads();

    // quantized output (straight-through, reference rounding) + loss partial
    double lsum = 0.0;
    #pragma unroll 2
    for (int i = tid; i < DIM * ROWS; i += THREADS) {
        int d = i >> 7, r = i & 127;
        float q = g_emb_t[(size_t)d * K_CODES + bidx[r]];
        float x = xbase[(size_t)d * TLEN + r];
        float diff = __fsub_rn(q, x);
        lsum += (double)diff * (double)diff;
        out[(size_t)b * DIM * TLEN + (size_t)d * TLEN + t0 + r] = __fadd_rn(x, diff);
    }
    #pragma unroll
    for (int o = 16; o > 0; o >>= 1)
        lsum += __shfl_down_sync(0xffffffffu, lsum, o);
    __shared__ double lred[32];
    if ((tid & 31) == 0) lred[tid >> 5] = lsum;
    __syncthreads();
    if (tid == 0) {
        double s = 0.0;
        #pragma unroll
        for (int wv = 0; wv < 32; ++wv) s += lred[wv];
        atomicAdd(&g_loss, s);
    }
}

// ---------------------------------------------------------------------------
__global__ void vq_finalize(float* __restrict__ out) {
    out[LOSS_OFF] = (float)(g_loss * 1.25 / (double)QELEMS);
}

// ---------------------------------------------------------------------------
extern "C" void kernel_launch(void* const* d_in, const int* in_sizes, int n_in,
                              void* d_out, int out_size) {
    const float* x_in = (const float*)d_in[0];   // [B, D, T] float32
    const float* emb  = (const float*)d_in[1];   // [K, D]    float32
    float* out = (float*)d_out;

    static int smem_set = 0;
    if (!smem_set) {
        cudaFuncSetAttribute(vq_main, cudaFuncAttributeMaxDynamicSharedMemorySize,
                             SMEM_SZ);
        smem_set = 1;
    }

    vq_prep<<<K_CODES, DIM>>>(emb);
    vq_main<<<NROWS / ROWS, THREADS, SMEM_SZ>>>(x_in, emb, out);
    vq_finalize<<<1, 1>>>(out);
}

// round 16
// speedup vs baseline: 1.7139x; 1.7139x over previous
#include <cuda_runtime.h>
#include <cuda_fp16.h>
#include <cstdint>
#include <cfloat>

// Problem constants
#define K_CODES 1024
#define DIM     256
#define BATCH   32
#define TLEN    2048
#define NROWS   (BATCH * TLEN)                 // 65536
#define QELEMS  ((size_t)BATCH * DIM * TLEN)   // 16777216
#define LOSS_OFF ((size_t)16777216)
#define IDX_OFF  ((size_t)16777217)

#define ROWS 128
#define THREADS 1024
#define KTILE  128
#define NTILES (K_CODES / KTILE)   // 8
#define AST 264                    // padded k-stride in halves (528B rows)
#define EH_BYTES (KTILE * AST * 2) // 67584 per buffer

// Scratch (no allocations allowed)
__device__ float  g_emb_t[DIM * K_CODES];   // transposed codebook [d][k]
__device__ float  g_esq[K_CODES];           // ||e_k||^2 exact (rescore)
__device__ float  g_sesq[K_CODES];          // 512 * ||e_k||^2 (approx ranking)
__device__ __half g_emb_h[K_CODES * DIM];   // fp16(1024 * e) [k][d]
__device__ double g_loss;

// Dynamic smem offsets (bytes)
#define OFF_AH    0                 // [128 rows][264 halves]
#define OFF_EH    67584             // 2 x [128 codes][264 halves]
#define OFF_SESQ  202752            // [1024] float (512*esq)
#define OFF_TMIN  206848            // [8][128] unsigned (encoded float)
#define OFF_MASK  210944            // [8][128][4] unsigned
#define OFF_WIN   227328            // [128] u64
#define OFF_XSQ   228352            // [128] float
#define OFF_MARG  228864            // [128] float
#define OFF_GMIN  229376            // [128] float
#define OFF_BIDX  229888            // [128] int
#define SMEM_SZ   230400

__device__ __forceinline__ void mma16816(float c[4], const unsigned a[4], const unsigned b[2]) {
    asm volatile(
        "mma.sync.aligned.m16n8k16.row.col.f32.f16.f16.f32 "
        "{%0,%1,%2,%3}, {%4,%5,%6,%7}, {%8,%9}, {%0,%1,%2,%3};"
        : "+f"(c[0]), "+f"(c[1]), "+f"(c[2]), "+f"(c[3])
        : "r"(a[0]), "r"(a[1]), "r"(a[2]), "r"(a[3]), "r"(b[0]), "r"(b[1]));
}

__device__ __forceinline__ void ldsm_x4(unsigned r[4], const void* p) {
    unsigned addr = (unsigned)__cvta_generic_to_shared(p);
    asm volatile("ldmatrix.sync.aligned.m8n8.x4.shared.b16 {%0,%1,%2,%3}, [%4];"
                 : "=r"(r[0]), "=r"(r[1]), "=r"(r[2]), "=r"(r[3]) : "r"(addr));
}

__device__ __forceinline__ void cp_async16(unsigned dst, const void* src) {
    asm volatile("cp.async.cg.shared.global [%0], [%1], 16;"
                 :: "r"(dst), "l"(src) : "memory");
}

// monotone float<->unsigned map
__device__ __forceinline__ unsigned fenc(float f) {
    unsigned b = __float_as_uint(f);
    return b ^ ((unsigned)((int)b >> 31) | 0x80000000u);
}
__device__ __forceinline__ float fdec(unsigned u) {
    unsigned b = u ^ (((int)u >= 0) ? 0xFFFFFFFFu : 0x80000000u);
    return __uint_as_float(b);
}

// ---------------------------------------------------------------------------
// prep: transpose codebook, ||e||^2 (+512x), fp16 scaled codebook, zero loss
// ---------------------------------------------------------------------------
__global__ void vq_prep(const float* __restrict__ emb) {
    int k = blockIdx.x;
    int d = threadIdx.x;
    float v = emb[k * DIM + d];
    g_emb_t[(size_t)d * K_CODES + k] = v;
    g_emb_h[(size_t)k * DIM + d] = __float2half(v * 1024.0f);

    __shared__ float red[DIM];
    red[d] = v * v;
    __syncthreads();
    #pragma unroll
    for (int s = DIM / 2; s > 0; s >>= 1) {
        if (d < s) red[d] += red[d + s];
        __syncthreads();
    }
    if (d == 0) { g_esq[k] = red[0]; g_sesq[k] = 512.0f * red[0]; }
    if (k == 0 && d == 0) g_loss = 0.0;
}

// ---------------------------------------------------------------------------
// main: f32-accum HMMA, 32 warps (16 rows x 32 codes each), cp.async staging
// grid: 512 blocks x 1024 threads, 225KB dyn smem (1 CTA/SM)
// ---------------------------------------------------------------------------
__global__ void __launch_bounds__(THREADS)
vq_main(const float* __restrict__ x_in, const float* __restrict__ emb,
        float* __restrict__ out) {
    extern __shared__ char sm[];
    float*  sesq = (float*)(sm + OFF_SESQ);
    unsigned* tmin = (unsigned*)(sm + OFF_TMIN);
    unsigned* cmask = (unsigned*)(sm + OFF_MASK);
    unsigned long long* winner = (unsigned long long*)(sm + OFF_WIN);
    float*  xsqs = (float*)(sm + OFF_XSQ);
    float*  margA = (float*)(sm + OFF_MARG);
    float*  gmin = (float*)(sm + OFF_GMIN);
    int*    bidx = (int*)(sm + OFF_BIDX);

    const unsigned smem_base = (unsigned)__cvta_generic_to_shared(sm);
    const int tid = threadIdx.x;
    const int blk = blockIdx.x;
    const int b   = blk >> 4;
    const int t0  = (blk & 15) * ROWS;
    const float* xbase = x_in + (size_t)b * DIM * TLEN + t0;

    // init scratch
    for (int i = tid; i < NTILES * ROWS; i += THREADS) tmin[i] = 0xFFFFFFFFu;
    for (int i = tid; i < NTILES * ROWS * 4; i += THREADS) cmask[i] = 0u;
    if (tid < ROWS) winner[tid] = ~0ull;
    for (int i = tid; i < K_CODES; i += THREADS) sesq[i] = g_sesq[i];

    // prefetch E tile 0 (64KB = 4096 x 16B)
    {
        const char* srcb = (const char*)g_emb_h;
        #pragma unroll
        for (int l = 0; l < 4; ++l) {
            int idx = tid + l * THREADS;
            int code = idx >> 5, j = idx & 31;
            cp_async16(smem_base + OFF_EH + code * (AST * 2) + j * 16,
                       srcb + code * 512 + j * 16);
        }
        asm volatile("cp.async.commit_group;" ::: "memory");
    }

    // A tile: fp16(x) as half2 pairs (coalesced along r)
    for (int i = tid; i < 128 * ROWS; i += THREADS) {
        int d2 = i >> 7, r = i & 127;
        float v0 = xbase[(size_t)(2 * d2) * TLEN + r];
        float v1 = xbase[(size_t)(2 * d2 + 1) * TLEN + r];
        *(__half2*)(sm + OFF_AH + r * (AST * 2) + d2 * 4) = __floats2half2_rn(v0, v1);
    }

    // ||x||^2 (exact sequential fp32 chain) + margin (dist'-units = 512x)
    if (tid < ROWS) {
        float s = 0.f, sa = 0.f;
        #pragma unroll 8
        for (int d = 0; d < DIM; ++d) {
            float v = xbase[(size_t)d * TLEN + tid];
            s = __fmaf_rn(v, v, s);
            sa += fabsf(v);
        }
        xsqs[tid] = s;
        margA[tid] = 512.0f * (sa * (4.0f / (1024.0f * 1024.0f)) + 3e-4f);
    }
    __syncthreads();

    const int lane = tid & 31, w = tid >> 5;
    const int g = lane >> 2, tk2 = lane & 3;
    const int r0 = (w & 7) * 16;   // warp's 16 rows
    const int c0 = (w >> 3) * 32;  // warp's 32 codes within 128-code tile

    for (int kt = 0; kt < NTILES; ++kt) {
        asm volatile("cp.async.wait_group 0;" ::: "memory");
        __syncthreads();   // tile kt staged; all warps done reading tile kt-1

        // prefetch tile kt+1 into the other buffer (overlaps this tile's MMA)
        if (kt + 1 < NTILES) {
            const char* srcb = (const char*)g_emb_h + (size_t)(kt + 1) * KTILE * DIM * 2;
            unsigned dbase = smem_base + OFF_EH + ((kt + 1) & 1) * EH_BYTES;
            #pragma unroll
            for (int l = 0; l < 4; ++l) {
                int idx = tid + l * THREADS;
                int code = idx >> 5, j = idx & 31;
                cp_async16(dbase + code * (AST * 2) + j * 16,
                           srcb + code * 512 + j * 16);
            }
            asm volatile("cp.async.commit_group;" ::: "memory");
        }

        const char* EhT = sm + OFF_EH + (kt & 1) * EH_BYTES;

        float acc[4][4];
        #pragma unroll
        for (int nn = 0; nn < 4; ++nn)
            #pragma unroll
            for (int c = 0; c < 4; ++c) acc[nn][c] = 0.f;

        #pragma unroll
        for (int kb = 0; kb < DIM; kb += 16) {
            unsigned a[4], bf[4][2];
            {
                int rowA = r0 + (lane & 15);
                int colA = kb + ((lane & 16) >> 1);
                ldsm_x4(a, sm + OFF_AH + rowA * (AST * 2) + colA * 2);
            }
            #pragma unroll
            for (int nn2 = 0; nn2 < 2; ++nn2) {
                int nrow = c0 + nn2 * 16 + (lane & 7) + ((lane & 16) >> 1);
                int colB = kb + (lane & 8);
                unsigned r4[4];
                ldsm_x4(r4, EhT + nrow * (AST * 2) + colB * 2);
                bf[2 * nn2][0] = r4[0]; bf[2 * nn2][1] = r4[1];
                bf[2 * nn2 + 1][0] = r4[2]; bf[2 * nn2 + 1][1] = r4[3];
            }
            #pragma unroll
            for (int nn = 0; nn < 4; ++nn)
                mma16816(acc[nn], a, bf[nn]);
        }

        // pass 1: dist' = 512*esq - acc; per-row min (register-only)
        float sq[8];
        #pragma unroll
        for (int nn = 0; nn < 4; ++nn) {
            sq[nn * 2]     = sesq[kt * KTILE + c0 + nn * 8 + 2 * tk2];
            sq[nn * 2 + 1] = sesq[kt * KTILE + c0 + nn * 8 + 2 * tk2 + 1];
        }
        float rmin[2] = {FLT_MAX, FLT_MAX};
        #pragma unroll
        for (int nn = 0; nn < 4; ++nn)
            #pragma unroll
            for (int c = 0; c < 4; ++c) {
                float d = __fsub_rn(sq[nn * 2 + (c & 1)], acc[nn][c]);
                acc[nn][c] = d;
                rmin[c >> 1] = fminf(rmin[c >> 1], d);
            }
        #pragma unroll
        for (int ch = 0; ch < 2; ++ch) {
            float v = rmin[ch];
            v = fminf(v, __shfl_xor_sync(0xffffffffu, v, 1));
            v = fminf(v, __shfl_xor_sync(0xffffffffu, v, 2));
            if (tk2 == 0)
                atomicMin(&tmin[kt * ROWS + r0 + g + ch * 8], fenc(v));
        }
        __syncthreads();

        // pass 2: flag candidates within margin of tile-min
        float lim[2];
        #pragma unroll
        for (int ch = 0; ch < 2; ++ch) {
            int row = r0 + g + ch * 8;
            lim[ch] = fdec(tmin[kt * ROWS + row]) + margA[row];
        }
        #pragma unroll
        for (int nn = 0; nn < 4; ++nn)
            #pragma unroll
            for (int c = 0; c < 4; ++c) {
                if (acc[nn][c] <= lim[c >> 1]) {
                    int kloc = c0 + nn * 8 + 2 * tk2 + (c & 1);
                    int row  = r0 + g + (c >> 1) * 8;
                    atomicOr(&cmask[(kt * ROWS + row) * 4 + (kloc >> 5)],
                             1u << (kloc & 31));
                }
            }
    }
    __syncthreads();

    // global approx min per row (dist'-units)
    if (tid < ROWS) {
        float m = FLT_MAX;
        #pragma unroll
        for (int t = 0; t < NTILES; ++t)
            m = fminf(m, fdec(tmin[t * ROWS + tid]));
        gmin[tid] = m;
    }
    __syncthreads();

    // exact rescore of candidates (identical fp32 fma chain as rounds 1-9)
    for (int p = tid; p < ROWS * NTILES; p += THREADS) {
        int r = p >> 3, t = p & 7;
        if (fdec(tmin[t * ROWS + r]) <= gmin[r] + margA[r]) {
            #pragma unroll
            for (int w4 = 0; w4 < 4; ++w4) {
                unsigned m = cmask[(t * ROWS + r) * 4 + w4];
                while (m) {
                    int bit = __ffs(m) - 1; m &= m - 1;
                    int k = t * KTILE + w4 * 32 + bit;
                    const float* ek = emb + (size_t)k * DIM;
                    float accv = 0.f;
                    #pragma unroll 8
                    for (int d = 0; d < DIM; ++d)
                        accv = __fmaf_rn(xbase[(size_t)d * TLEN + r], ek[d], accv);
                    float dd = __fsub_rn(__fadd_rn(xsqs[r], g_esq[k]),
                                         __fmul_rn(2.0f, accv));
                    unsigned long long key =
                        ((unsigned long long)__float_as_uint(dd) << 32) | (unsigned)k;
                    atomicMin(&winner[r], key);
                }
            }
        }
    }
    __syncthreads();

    if (tid < ROWS) {
        int bi = (int)(winner[tid] & 0xffffffffu);
        bidx[tid] = bi;
        out[IDX_OFF + (size_t)b * TLEN + t0 + tid] = (float)bi;
    }
    __syncthreads();

    // quantized output (straight-through, reference rounding) + loss partial
    double lsum = 0.0;
    #pragma unroll 2
    for (int i = tid; i < DIM * ROWS; i += THREADS) {
        int d = i >> 7, r = i & 127;
        float q = g_emb_t[(size_t)d * K_CODES + bidx[r]];
        float x = xbase[(size_t)d * TLEN + r];
        float diff = __fsub_rn(q, x);
        lsum += (double)diff * (double)diff;
        out[(size_t)b * DIM * TLEN + (size_t)d * TLEN + t0 + r] = __fadd_rn(x, diff);
    }
    #pragma unroll
    for (int o = 16; o > 0; o >>= 1)
        lsum += __shfl_down_sync(0xffffffffu, lsum, o);
    __shared__ double lred[32];
    if ((tid & 31) == 0) lred[tid >> 5] = lsum;
    __syncthreads();
    if (tid == 0) {
        double s = 0.0;
        #pragma unroll
        for (int wv = 0; wv < 32; ++wv) s += lred[wv];
        atomicAdd(&g_loss, s);
    }
}

// ---------------------------------------------------------------------------
__global__ void vq_finalize(float* __restrict__ out) {
    out[LOSS_OFF] = (float)(g_loss * 1.25 / (double)QELEMS);
}

// ---------------------------------------------------------------------------
extern "C" void kernel_launch(void* const* d_in, const int* in_sizes, int n_in,
                              void* d_out, int out_size) {
    const float* x_in = (const float*)d_in[0];   // [B, D, T] float32
    const float* emb  = (const float*)d_in[1];   // [K, D]    float32
    float* out = (float*)d_out;

    static int smem_set = 0;
    if (!smem_set) {
        cudaFuncSetAttribute(vq_main, cudaFuncAttributeMaxDynamicSharedMemorySize,
                             SMEM_SZ);
        smem_set = 1;
    }

    vq_prep<<<K_CODES, DIM>>>(emb);
    vq_main<<<NROWS / ROWS, THREADS, SMEM_SZ>>>(x_in, emb, out);
    vq_finalize<<<1, 1>>>(out);
}